// round 8
// baseline (speedup 1.0000x reference)
#include <cuda_runtime.h>

#define NMAX 100000
#define EMAX 1500000

// Static scratch (allocation-free rule).
static __device__ __align__(16) float g_agg[NMAX * 64];   // 25.6 MB
static __device__ __align__(8)  int2  g_pairs[EMAX];      // {src, w bits} 12 MB
static __device__ int g_counts[NMAX];
static __device__ int g_offsets[NMAX];
static __device__ int g_cursor[NMAX];
static __device__ int g_blocksums[128];                   // ceil(NMAX/1024)=98

// ---------------------------------------------------------------------------
// In-block edge-index dtype detect (JAX demotes int64->int32 when x64 off).
// Warp 0 samples 32 int64 slots (in-bounds under both interpretations: the
// int32 buffer spans E int64 slots); int32 pairs have random high words ->
// out of range. Result broadcast via shared. Costs one L2 round per block.
// ---------------------------------------------------------------------------
__device__ __forceinline__ int block_detect_is64(
    const long long* ei, int E, int n_src, int* sflag)
{
    if (threadIdx.x < 32) {
        long long stride = (E > 32) ? (E / 32) : 1;
        long long idx = (long long)threadIdx.x * stride;
        if (idx > E - 1) idx = E - 1;
        long long v = ei[idx];
        bool bad = (v < 0 || v >= n_src);
        unsigned m = __ballot_sync(0xffffffffu, bad);
        if (threadIdx.x == 0) *sflag = (m == 0) ? 1 : 0;
    }
    __syncthreads();
    return *sflag;
}

// ---------------------------------------------------------------------------
// Histogram of dst indices.
// ---------------------------------------------------------------------------
__global__ void __launch_bounds__(256) hist_kernel(
    const void* __restrict__ ei_raw, int E, int n_src)
{
    __shared__ int sflag;
    int is64 = block_detect_is64((const long long*)ei_raw, E, n_src, &sflag);
    int e = blockIdx.x * blockDim.x + threadIdx.x;
    if (e >= E) return;
    int d = is64 ? (int)((const long long*)ei_raw)[(long long)E + e]
                 : ((const int*)ei_raw)[(long long)E + e];
    atomicAdd(&g_counts[d], 1);
}

// ---------------------------------------------------------------------------
// Per-1024-chunk reduction of counts -> g_blocksums.
// ---------------------------------------------------------------------------
__global__ void __launch_bounds__(1024) blockreduce_kernel(int n)
{
    __shared__ int sdata[1024];
    int i = blockIdx.x * 1024 + threadIdx.x;
    sdata[threadIdx.x] = (i < n) ? g_counts[i] : 0;
    __syncthreads();
    #pragma unroll
    for (int s = 512; s > 0; s >>= 1) {
        if (threadIdx.x < s) sdata[threadIdx.x] += sdata[threadIdx.x + s];
        __syncthreads();
    }
    if (threadIdx.x == 0) g_blocksums[blockIdx.x] = sdata[0];
}

// ---------------------------------------------------------------------------
// Parallel exclusive scan of <=128 block sums (one 128-thread block).
// ---------------------------------------------------------------------------
__global__ void __launch_bounds__(128) scan_sums_kernel(int nb)
{
    __shared__ int s[128];
    int tid = threadIdx.x;
    int v = (tid < nb) ? g_blocksums[tid] : 0;
    s[tid] = v;
    __syncthreads();
    #pragma unroll
    for (int d = 1; d < 128; d <<= 1) {
        int t = (tid >= d) ? s[tid - d] : 0;
        __syncthreads();
        s[tid] += t;
        __syncthreads();
    }
    if (tid < nb) g_blocksums[tid] = s[tid] - v;   // exclusive
}

// ---------------------------------------------------------------------------
// Per-chunk exclusive scan + chunk offset -> offsets, cursor.
// ---------------------------------------------------------------------------
__global__ void __launch_bounds__(1024) blockscan_kernel(int n)
{
    __shared__ int sdata[1024];
    int i = blockIdx.x * 1024 + threadIdx.x;
    int v = (i < n) ? g_counts[i] : 0;
    sdata[threadIdx.x] = v;
    __syncthreads();
    #pragma unroll
    for (int s = 1; s < 1024; s <<= 1) {
        int t = (threadIdx.x >= s) ? sdata[threadIdx.x - s] : 0;
        __syncthreads();
        sdata[threadIdx.x] += t;
        __syncthreads();
    }
    if (i < n) {
        int excl = sdata[threadIdx.x] - v + g_blocksums[blockIdx.x];
        g_offsets[i] = excl;
        g_cursor[i]  = excl;
    }
}

// ---------------------------------------------------------------------------
// Reorder edges into dst-contiguous pairs {src, w bits}.
// ---------------------------------------------------------------------------
__global__ void __launch_bounds__(256) reorder_kernel(
    const void* __restrict__ ei_raw, const float* __restrict__ ew,
    int E, int n_src)
{
    __shared__ int sflag;
    int is64 = block_detect_is64((const long long*)ei_raw, E, n_src, &sflag);
    int e = blockIdx.x * blockDim.x + threadIdx.x;
    if (e >= E) return;
    int s, d;
    if (is64) {
        const long long* ei = (const long long*)ei_raw;
        s = (int)ei[e]; d = (int)ei[(long long)E + e];
    } else {
        const int* ei = (const int*)ei_raw;
        s = ei[e]; d = ei[(long long)E + e];
    }
    int pos = atomicAdd(&g_cursor[d], 1);
    g_pairs[pos] = make_int2(s, __float_as_int(ew[e]));
}

// ---------------------------------------------------------------------------
// Atomic-free accumulate: agg[dst] = sum_{edges of dst} w * x_src[src].
// 16 lanes per dst (2 dsts/warp); each lane owns one float4 column slot.
// All 16 lanes read the same pair (L2 broadcast, 1 sector) with next-pair
// prefetch to overlap the pair->gather dependency chain. Writes every row
// (cnt==0 -> zeros), so g_agg needs no memset.
// ---------------------------------------------------------------------------
__global__ void __launch_bounds__(256) accumulate_kernel(
    const float* __restrict__ xsrc, int n_dst)
{
    const int t = blockIdx.x * blockDim.x + threadIdx.x;
    const int lane = t & 15;
    const int dst  = t >> 4;
    if (dst >= n_dst) return;

    const int off = g_offsets[dst];
    const int cnt = g_counts[dst];

    float4 acc = make_float4(0.f, 0.f, 0.f, 0.f);
    int2 p = (cnt > 0) ? g_pairs[off] : make_int2(0, 0);
    for (int j = 0; j < cnt; ) {
        int2 cur = p;
        ++j;
        if (j < cnt) p = g_pairs[off + j];          // prefetch next pair
        const float w = __int_as_float(cur.y);
        float4 v = *(const float4*)(xsrc + (size_t)cur.x * 64 + lane * 4);
        acc.x = fmaf(v.x, w, acc.x);
        acc.y = fmaf(v.y, w, acc.y);
        acc.z = fmaf(v.z, w, acc.z);
        acc.w = fmaf(v.w, w, acc.w);
    }
    *(float4*)(g_agg + (size_t)dst * 64 + lane * 4) = acc;
}

// ---------------------------------------------------------------------------
// Fallback atomic scatter (only if sizes exceed static capacity).
// ---------------------------------------------------------------------------
__global__ void __launch_bounds__(256) scatter_atomic_kernel(
    const float* __restrict__ xsrc, const void* __restrict__ ei_raw,
    const float* __restrict__ ew, float* __restrict__ agg, int E, int n_src)
{
    __shared__ int sflag;
    int is64 = block_detect_is64((const long long*)ei_raw, E, n_src, &sflag);
    const long long t = (long long)blockIdx.x * blockDim.x + threadIdx.x;
    const int lane = (int)(t & 15);
    const long long e0 = (t >> 4) * 8;
    if (e0 >= E) return;
    const int n = (E - e0 >= 8) ? 8 : (int)(E - e0);

    int s[8], d[8];
    float w[8];
    if (is64) {
        const long long* ei = (const long long*)ei_raw;
        #pragma unroll
        for (int i = 0; i < 8; i++) if (i < n) {
            s[i] = (int)ei[e0 + i]; d[i] = (int)ei[(long long)E + e0 + i];
        }
    } else {
        const int* ei = (const int*)ei_raw;
        #pragma unroll
        for (int i = 0; i < 8; i++) if (i < n) {
            s[i] = ei[e0 + i]; d[i] = ei[(long long)E + e0 + i];
        }
    }
    #pragma unroll
    for (int i = 0; i < 8; i++) if (i < n) w[i] = ew[e0 + i];
    #pragma unroll
    for (int i = 0; i < 8; i++) if (i < n) {
        float4 v = *(const float4*)(xsrc + (size_t)s[i] * 64 + lane * 4);
        v.x *= w[i]; v.y *= w[i]; v.z *= w[i]; v.w *= w[i];
        float* dp = agg + (size_t)d[i] * 64 + lane * 4;
        asm volatile("red.global.add.v4.f32 [%0], {%1, %2, %3, %4};"
                     :: "l"(dp), "f"(v.x), "f"(v.y), "f"(v.z), "f"(v.w)
                     : "memory");
    }
}

// ---------------------------------------------------------------------------
// tf32 helpers + fused GEMM (proven round-7 kernel):
//   out = x_dst @ W_self^T + g_agg @ W_nei^T + b   (N x 64)
// ---------------------------------------------------------------------------
__device__ __forceinline__ unsigned f2tf32(float x) {
    unsigned u;
    asm("cvt.rna.tf32.f32 %0, %1;" : "=r"(u) : "f"(x));
    return u;
}

#define MMA_TF32(c0, c1, c2, c3, a0, a1, a2, a3, b0, b1)                     \
    asm volatile(                                                            \
        "mma.sync.aligned.m16n8k8.row.col.f32.tf32.tf32.f32 "               \
        "{%0,%1,%2,%3}, {%4,%5,%6,%7}, {%8,%9}, {%0,%1,%2,%3};"             \
        : "+f"(c0), "+f"(c1), "+f"(c2), "+f"(c3)                             \
        : "r"(a0), "r"(a1), "r"(a2), "r"(a3), "r"(b0), "r"(b1))

#define AS_STRIDE 68
#define BS_STRIDE 132
#define AS_FLOATS (128 * AS_STRIDE)
#define BS_FLOATS (64 * BS_STRIDE)
#define GEMM_SMEM_BYTES ((AS_FLOATS + BS_FLOATS) * 4)

__global__ void __launch_bounds__(256) fused_gemm_tf32_kernel(
    const float* __restrict__ Xd, const float* __restrict__ Wself,
    const float* __restrict__ Wnei, const float* __restrict__ bias,
    float* __restrict__ out, int N)
{
    extern __shared__ __align__(16) float smem[];
    float* As = smem;                 // [128][AS_STRIDE]
    float* Bs = smem + AS_FLOATS;     // [64][BS_STRIDE]

    const int tid  = threadIdx.x;
    const int lane = tid & 31;
    const int wid  = tid >> 5;
    const int g    = lane >> 2;
    const int tg   = lane & 3;
    const int wr   = wid * 16;
    const int rowbase = blockIdx.x * 128;

    #pragma unroll
    for (int m = 0; m < 2; m++) {
        const float* Wm = m ? Wnei : Wself;
        #pragma unroll
        for (int i = 0; i < 4; i++) {
            int f  = tid + i * 256;
            int c  = f >> 4;
            int k4 = f & 15;
            float4 v = *(const float4*)(Wm + c * 64 + k4 * 4);
            float* b = Bs + c * BS_STRIDE + m * 64 + k4 * 4;
            b[0] = __uint_as_float(f2tf32(v.x));
            b[1] = __uint_as_float(f2tf32(v.y));
            b[2] = __uint_as_float(f2tf32(v.z));
            b[3] = __uint_as_float(f2tf32(v.w));
        }
    }

    float acc[8][4];
    #pragma unroll
    for (int nt = 0; nt < 8; nt++) {
        float b0 = bias[nt * 8 + 2 * tg];
        float b1 = bias[nt * 8 + 2 * tg + 1];
        acc[nt][0] = b0; acc[nt][1] = b1;
        acc[nt][2] = b0; acc[nt][3] = b1;
    }

    const float* aggp = g_agg;

    #pragma unroll 1
    for (int h = 0; h < 2; h++) {
        const float* Xsrc = h ? aggp : Xd;
        __syncthreads();
        #pragma unroll
        for (int i = 0; i < 8; i++) {
            int f  = tid + i * 256;
            int r  = f >> 4;
            int k4 = f & 15;
            int gr = rowbase + r;
            float4 v = make_float4(0.f, 0.f, 0.f, 0.f);
            if (gr < N) v = *(const float4*)(Xsrc + (size_t)gr * 64 + k4 * 4);
            float4 cv;
            cv.x = __uint_as_float(f2tf32(v.x));
            cv.y = __uint_as_float(f2tf32(v.y));
            cv.z = __uint_as_float(f2tf32(v.z));
            cv.w = __uint_as_float(f2tf32(v.w));
            *(float4*)(As + r * AS_STRIDE + k4 * 4) = cv;
        }
        __syncthreads();

        #pragma unroll
        for (int kc = 0; kc < 8; kc++) {
            const int k0 = kc * 8;
            const float* arow0 = As + (wr + g) * AS_STRIDE + k0;
            const float* arow1 = arow0 + 8 * AS_STRIDE;
            unsigned a0 = __float_as_uint(arow0[tg]);
            unsigned a1 = __float_as_uint(arow1[tg]);
            unsigned a2 = __float_as_uint(arow0[tg + 4]);
            unsigned a3 = __float_as_uint(arow1[tg + 4]);
            #pragma unroll
            for (int nt = 0; nt < 8; nt++) {
                const float* brow = Bs + (nt * 8 + g) * BS_STRIDE + h * 64 + k0;
                unsigned b0 = __float_as_uint(brow[tg]);
                unsigned b1 = __float_as_uint(brow[tg + 4]);
                MMA_TF32(acc[nt][0], acc[nt][1], acc[nt][2], acc[nt][3],
                         a0, a1, a2, a3, b0, b1);
            }
        }
    }

    const int r0 = rowbase + wr + g;
    const int r1 = r0 + 8;
    if (r0 < N) {
        float* yrow = out + (size_t)r0 * 64;
        #pragma unroll
        for (int nt = 0; nt < 8; nt++)
            *(float2*)(yrow + nt * 8 + 2 * tg) = make_float2(acc[nt][0], acc[nt][1]);
    }
    if (r1 < N) {
        float* yrow = out + (size_t)r1 * 64;
        #pragma unroll
        for (int nt = 0; nt < 8; nt++)
            *(float2*)(yrow + nt * 8 + 2 * tg) = make_float2(acc[nt][2], acc[nt][3]);
    }
}

// ---------------------------------------------------------------------------
// Inputs: 0:x_src f32[Ns*64] 1:x_dst f32[Nd*64] 2:edge_index[2E] (i32/i64)
//         3:edge_weight f32[E] 4:W_nei [64,64] 5:W_self [64,64] 6:b_self [64]
// Output: f32 [Nd*64]
// ---------------------------------------------------------------------------
extern "C" void kernel_launch(void* const* d_in, const int* in_sizes, int n_in,
                              void* d_out, int out_size)
{
    const float* x_src  = (const float*)d_in[0];
    const float* x_dst  = (const float*)d_in[1];
    const void*  ei     = d_in[2];
    const float* ew     = (const float*)d_in[3];
    const float* W_nei  = (const float*)d_in[4];
    const float* W_self = (const float*)d_in[5];
    const float* b_self = (const float*)d_in[6];
    float*       out    = (float*)d_out;

    const int n_src = in_sizes[0] / 64;
    const int n_dst = in_sizes[1] / 64;
    const int E     = in_sizes[3];

    if (E <= EMAX && n_dst <= NMAX) {
        // ---- CSR-by-dst path (atomic-free accumulate) ----
        int* countsp = nullptr;
        cudaGetSymbolAddress((void**)&countsp, g_counts);
        cudaMemsetAsync(countsp, 0, (size_t)n_dst * sizeof(int));

        hist_kernel<<<(E + 255) / 256, 256>>>(ei, E, n_src);

        const int NB = (n_dst + 1023) / 1024;
        blockreduce_kernel<<<NB, 1024>>>(n_dst);
        scan_sums_kernel<<<1, 128>>>(NB);
        blockscan_kernel<<<NB, 1024>>>(n_dst);

        reorder_kernel<<<(E + 255) / 256, 256>>>(ei, ew, E, n_src);

        {
            long long threads = (long long)n_dst * 16;
            int blocks = (int)((threads + 255) / 256);
            accumulate_kernel<<<blocks, 256>>>(x_src, n_dst);
        }
    } else {
        // ---- fallback: atomic scatter into zeroed agg ----
        float* aggp = nullptr;
        cudaGetSymbolAddress((void**)&aggp, g_agg);
        cudaMemsetAsync(aggp, 0, (size_t)n_dst * 64 * sizeof(float));
        long long groups  = ((long long)E + 7) / 8;
        long long threads = groups * 16;
        int blocks = (int)((threads + 255) / 256);
        scatter_atomic_kernel<<<blocks, 256>>>(x_src, ei, ew, aggp, E, n_src);
    }

    // fused tf32 GEMM: out = x_dst @ W_self^T + agg @ W_nei^T + b
    static int smem_set = 0;
    if (!smem_set) {
        cudaFuncSetAttribute(fused_gemm_tf32_kernel,
                             cudaFuncAttributeMaxDynamicSharedMemorySize,
                             GEMM_SMEM_BYTES);
        smem_set = 1;
    }
    fused_gemm_tf32_kernel<<<(n_dst + 127) / 128, 256, GEMM_SMEM_BYTES>>>(
        x_dst, W_self, W_nei, b_self, out, n_dst);
}

// round 9
// speedup vs baseline: 1.1356x; 1.1356x over previous
#include <cuda_runtime.h>

#define NMAX 100000

// Aggregation buffer agg[dst] = sum_e w_e * x_src[src_e]; 25.6 MB static.
static __device__ __align__(16) float g_agg[NMAX * 64];

// ---------------------------------------------------------------------------
// In-block edge-index dtype detect (JAX demotes int64->int32 when x64 off).
// Warp 0 samples 32 int64 slots (in-bounds under both interpretations: the
// int32 buffer spans exactly E int64 slots); int32 pairs have random high
// words -> out of [0, n_src). Must run before any thread exits the block.
// ---------------------------------------------------------------------------
__device__ __forceinline__ int block_detect_is64(
    const long long* ei, int E, int n_src, int* sflag)
{
    if (threadIdx.x < 32) {
        long long stride = (E > 32) ? (E / 32) : 1;
        long long idx = (long long)threadIdx.x * stride;
        if (idx > E - 1) idx = E - 1;
        long long v = ei[idx];
        bool bad = (v < 0 || v >= n_src);
        unsigned m = __ballot_sync(0xffffffffu, bad);
        if (threadIdx.x == 0) *sflag = (m == 0) ? 1 : 0;
    }
    __syncthreads();
    return *sflag;
}

// ---------------------------------------------------------------------------
// Edge scatter (input space): g_agg[dst] += x_src[src] * w.
// 16 lanes per edge-group; each thread owns one float4 slot of 8 consecutive
// edges -> 8 independent L2 gathers in flight, then 8 vector REDs.
// ---------------------------------------------------------------------------
__global__ void __launch_bounds__(256) scatter_kernel(
    const float* __restrict__ xsrc,
    const void* __restrict__ ei_raw,    // [2, E]: src row then dst row
    const float* __restrict__ ew,       // [E]
    int E, int n_src)
{
    __shared__ int sflag;
    const int is64 = block_detect_is64((const long long*)ei_raw, E, n_src, &sflag);

    const long long t = (long long)blockIdx.x * blockDim.x + threadIdx.x;
    const int lane = (int)(t & 15);
    const long long e0 = (t >> 4) * 8;
    if (e0 >= E) return;
    const int n = (E - e0 >= 8) ? 8 : (int)(E - e0);

    int s[8], d[8];
    float w[8];
    if (is64) {
        const long long* ei = (const long long*)ei_raw;
        #pragma unroll
        for (int i = 0; i < 8; i++) if (i < n) {
            s[i] = (int)ei[e0 + i];
            d[i] = (int)ei[(long long)E + e0 + i];
        }
    } else {
        const int* ei = (const int*)ei_raw;
        #pragma unroll
        for (int i = 0; i < 8; i++) if (i < n) {
            s[i] = ei[e0 + i];
            d[i] = ei[(long long)E + e0 + i];
        }
    }
    #pragma unroll
    for (int i = 0; i < 8; i++) if (i < n) w[i] = ew[e0 + i];

    float4 v[8];
    #pragma unroll
    for (int i = 0; i < 8; i++) if (i < n)
        v[i] = *(const float4*)(xsrc + (size_t)s[i] * 64 + lane * 4);

    #pragma unroll
    for (int i = 0; i < 8; i++) if (i < n) {
        const float wi = w[i];
        float4 vv = v[i];
        vv.x *= wi; vv.y *= wi; vv.z *= wi; vv.w *= wi;
        float* dst = g_agg + (size_t)d[i] * 64 + lane * 4;
        asm volatile("red.global.add.v4.f32 [%0], {%1, %2, %3, %4};"
                     :: "l"(dst), "f"(vv.x), "f"(vv.y), "f"(vv.z), "f"(vv.w)
                     : "memory");
    }
}

// ---------------------------------------------------------------------------
// tf32 helpers
// ---------------------------------------------------------------------------
__device__ __forceinline__ unsigned f2tf32(float x) {
    unsigned u;
    asm("cvt.rna.tf32.f32 %0, %1;" : "=r"(u) : "f"(x));
    return u;
}

#define MMA_TF32(c0, c1, c2, c3, a0, a1, a2, a3, b0, b1)                     \
    asm volatile(                                                            \
        "mma.sync.aligned.m16n8k8.row.col.f32.tf32.tf32.f32 "               \
        "{%0,%1,%2,%3}, {%4,%5,%6,%7}, {%8,%9}, {%0,%1,%2,%3};"             \
        : "+f"(c0), "+f"(c1), "+f"(c2), "+f"(c3)                             \
        : "r"(a0), "r"(a1), "r"(a2), "r"(a3), "r"(b0), "r"(b1))

// ---------------------------------------------------------------------------
// Fused tf32 GEMM: out = x_dst @ W_self^T + g_agg @ W_nei^T + b   (N x 64)
// Block = 256 thr (8 warps); block tile 128 rows x 64 cols; warp w owns
// rows 16w..16w+15 x 64 cols (8 m16n8k8 n-tiles). Pipelined: As0 LDG issued
// before B staging; As1 LDG issued before the h=0 MMA loop, so global-load
// latency is hidden behind staging/compute.
// ---------------------------------------------------------------------------
#define AS_STRIDE 68
#define BS_STRIDE 132
#define AS_FLOATS (128 * AS_STRIDE)
#define BS_FLOATS (64 * BS_STRIDE)
#define GEMM_SMEM_BYTES ((AS_FLOATS + BS_FLOATS) * 4)

__global__ void __launch_bounds__(256) fused_gemm_tf32_kernel(
    const float* __restrict__ Xd, const float* __restrict__ Wself,
    const float* __restrict__ Wnei, const float* __restrict__ bias,
    float* __restrict__ out, int N)
{
    extern __shared__ __align__(16) float smem[];
    float* As = smem;                 // [128][AS_STRIDE]
    float* Bs = smem + AS_FLOATS;     // [64][BS_STRIDE]

    const int tid  = threadIdx.x;
    const int lane = tid & 31;
    const int wid  = tid >> 5;
    const int g    = lane >> 2;
    const int tg   = lane & 3;
    const int wr   = wid * 16;
    const int rowbase = blockIdx.x * 128;

    // Per-thread staging coordinates (8 float4 slots covering 128x64).
    int srow[8], sk4[8];
    bool sok[8];
    #pragma unroll
    for (int i = 0; i < 8; i++) {
        int f = tid + i * 256;
        srow[i] = f >> 4;
        sk4[i]  = f & 15;
        sok[i]  = (rowbase + srow[i]) < N;
    }

    // ---- issue As0 loads (x_dst) FIRST; flight hides behind B staging ----
    float4 areg[8];
    #pragma unroll
    for (int i = 0; i < 8; i++) {
        areg[i] = make_float4(0.f, 0.f, 0.f, 0.f);
        if (sok[i])
            areg[i] = *(const float4*)(Xd + (size_t)(rowbase + srow[i]) * 64 + sk4[i] * 4);
    }

    // ---- stage B (both W matrices), cvt to tf32 ----
    #pragma unroll
    for (int m = 0; m < 2; m++) {
        const float* Wm = m ? Wnei : Wself;
        #pragma unroll
        for (int i = 0; i < 4; i++) {
            int f  = tid + i * 256;
            int c  = f >> 4;
            int k4 = f & 15;
            float4 v = *(const float4*)(Wm + c * 64 + k4 * 4);
            float* b = Bs + c * BS_STRIDE + m * 64 + k4 * 4;
            b[0] = __uint_as_float(f2tf32(v.x));
            b[1] = __uint_as_float(f2tf32(v.y));
            b[2] = __uint_as_float(f2tf32(v.z));
            b[3] = __uint_as_float(f2tf32(v.w));
        }
    }

    // ---- store As0 to shared (cvt tf32) ----
    #pragma unroll
    for (int i = 0; i < 8; i++) {
        float4 cv;
        cv.x = __uint_as_float(f2tf32(areg[i].x));
        cv.y = __uint_as_float(f2tf32(areg[i].y));
        cv.z = __uint_as_float(f2tf32(areg[i].z));
        cv.w = __uint_as_float(f2tf32(areg[i].w));
        *(float4*)(As + srow[i] * AS_STRIDE + sk4[i] * 4) = cv;
    }

    // ---- accumulators init with bias ----
    float acc[8][4];
    #pragma unroll
    for (int nt = 0; nt < 8; nt++) {
        float b0 = bias[nt * 8 + 2 * tg];
        float b1 = bias[nt * 8 + 2 * tg + 1];
        acc[nt][0] = b0; acc[nt][1] = b1;
        acc[nt][2] = b0; acc[nt][3] = b1;
    }

    __syncthreads();

    // ---- issue As1 loads (agg); flight hides behind MMA0 ----
    const float* aggp = g_agg;
    #pragma unroll
    for (int i = 0; i < 8; i++) {
        float4 v = make_float4(0.f, 0.f, 0.f, 0.f);
        if (sok[i])
            v = *(const float4*)(aggp + (size_t)(rowbase + srow[i]) * 64 + sk4[i] * 4);
        areg[i] = v;
    }

    // ---- MMA over h=0 (W_self half) ----
    #pragma unroll
    for (int kc = 0; kc < 8; kc++) {
        const int k0 = kc * 8;
        const float* arow0 = As + (wr + g) * AS_STRIDE + k0;
        const float* arow1 = arow0 + 8 * AS_STRIDE;
        unsigned a0 = __float_as_uint(arow0[tg]);
        unsigned a1 = __float_as_uint(arow1[tg]);
        unsigned a2 = __float_as_uint(arow0[tg + 4]);
        unsigned a3 = __float_as_uint(arow1[tg + 4]);
        #pragma unroll
        for (int nt = 0; nt < 8; nt++) {
            const float* brow = Bs + (nt * 8 + g) * BS_STRIDE + k0;
            unsigned b0 = __float_as_uint(brow[tg]);
            unsigned b1 = __float_as_uint(brow[tg + 4]);
            MMA_TF32(acc[nt][0], acc[nt][1], acc[nt][2], acc[nt][3],
                     a0, a1, a2, a3, b0, b1);
        }
    }

    __syncthreads();

    // ---- store As1 to shared ----
    #pragma unroll
    for (int i = 0; i < 8; i++) {
        float4 cv;
        cv.x = __uint_as_float(f2tf32(areg[i].x));
        cv.y = __uint_as_float(f2tf32(areg[i].y));
        cv.z = __uint_as_float(f2tf32(areg[i].z));
        cv.w = __uint_as_float(f2tf32(areg[i].w));
        *(float4*)(As + srow[i] * AS_STRIDE + sk4[i] * 4) = cv;
    }
    __syncthreads();

    // ---- MMA over h=1 (W_nei half) ----
    #pragma unroll
    for (int kc = 0; kc < 8; kc++) {
        const int k0 = kc * 8;
        const float* arow0 = As + (wr + g) * AS_STRIDE + k0;
        const float* arow1 = arow0 + 8 * AS_STRIDE;
        unsigned a0 = __float_as_uint(arow0[tg]);
        unsigned a1 = __float_as_uint(arow1[tg]);
        unsigned a2 = __float_as_uint(arow0[tg + 4]);
        unsigned a3 = __float_as_uint(arow1[tg + 4]);
        #pragma unroll
        for (int nt = 0; nt < 8; nt++) {
            const float* brow = Bs + (nt * 8 + g) * BS_STRIDE + 64 + k0;
            unsigned b0 = __float_as_uint(brow[tg]);
            unsigned b1 = __float_as_uint(brow[tg + 4]);
            MMA_TF32(acc[nt][0], acc[nt][1], acc[nt][2], acc[nt][3],
                     a0, a1, a2, a3, b0, b1);
        }
    }

    // ---- store ----
    const int r0 = rowbase + wr + g;
    const int r1 = r0 + 8;
    if (r0 < N) {
        float* yrow = out + (size_t)r0 * 64;
        #pragma unroll
        for (int nt = 0; nt < 8; nt++)
            *(float2*)(yrow + nt * 8 + 2 * tg) = make_float2(acc[nt][0], acc[nt][1]);
    }
    if (r1 < N) {
        float* yrow = out + (size_t)r1 * 64;
        #pragma unroll
        for (int nt = 0; nt < 8; nt++)
            *(float2*)(yrow + nt * 8 + 2 * tg) = make_float2(acc[nt][2], acc[nt][3]);
    }
}

// ---------------------------------------------------------------------------
// Inputs: 0:x_src f32[Ns*64] 1:x_dst f32[Nd*64] 2:edge_index[2E] (i32/i64)
//         3:edge_weight f32[E] 4:W_nei [64,64] 5:W_self [64,64] 6:b_self [64]
// Output: f32 [Nd*64]
// ---------------------------------------------------------------------------
extern "C" void kernel_launch(void* const* d_in, const int* in_sizes, int n_in,
                              void* d_out, int out_size)
{
    const float* x_src  = (const float*)d_in[0];
    const float* x_dst  = (const float*)d_in[1];
    const void*  ei     = d_in[2];
    const float* ew     = (const float*)d_in[3];
    const float* W_nei  = (const float*)d_in[4];
    const float* W_self = (const float*)d_in[5];
    const float* b_self = (const float*)d_in[6];
    float*       out    = (float*)d_out;

    const int n_src = in_sizes[0] / 64;
    const int n_dst = in_sizes[1] / 64;
    const int E     = in_sizes[3];

    float* aggp = nullptr;
    cudaGetSymbolAddress((void**)&aggp, g_agg);

    // 0) zero agg
    cudaMemsetAsync(aggp, 0, (size_t)n_dst * 64 * sizeof(float));

    // 1) scatter in input space (8 edges per thread, 16 lanes/edge,
    //    dtype detect folded in)
    {
        long long groups  = ((long long)E + 7) / 8;
        long long threads = groups * 16;
        int blocks = (int)((threads + 255) / 256);
        scatter_kernel<<<blocks, 256>>>(x_src, ei, ew, E, n_src);
    }

    // 2) fused tf32 GEMM: out = x_dst @ W_self^T + agg @ W_nei^T + b
    static int smem_set = 0;
    if (!smem_set) {
        cudaFuncSetAttribute(fused_gemm_tf32_kernel,
                             cudaFuncAttributeMaxDynamicSharedMemorySize,
                             GEMM_SMEM_BYTES);
        smem_set = 1;
    }
    fused_gemm_tf32_kernel<<<(n_dst + 127) / 128, 256, GEMM_SMEM_BYTES>>>(
        x_dst, W_self, W_nei, b_self, out, n_dst);
}